// round 3
// baseline (speedup 1.0000x reference)
#include <cuda_runtime.h>
#include <math.h>

#define Bv 8
#define Cv 256
#define HWv 4096
#define NHv 4
#define HDv 64

// ---------------- scratch (device globals; no allocations) ----------------
__device__ float g_qln [Bv*Cv*HWv];        // 33.5 MB
__device__ float g_kvln[2*Bv*Cv*HWv];      // 67 MB
__device__ float g_q   [Bv*Cv*HWv];        // 33.5 MB
__device__ float g_kv  [2*Bv*2*Cv*HWv];    // 134 MB  (per bb: rows 0..255 = k, 256..511 = v)
__device__ float g_qinv[Bv*Cv];
__device__ float g_kinv[2*Bv*Cv];
__device__ float g_spart[8*2*Bv*NHv*HDv*HDv];  // split-K partials, 8 MB
__device__ float g_attn [2*Bv*NHv*HDv*HDv];    // gated softmax(P), 1 MB
__device__ float g_qkv [Bv*Cv*HWv];
__device__ float g_x   [Bv*Cv*HWv];
__device__ float g_yln [Bv*Cv*HWv];
__device__ float g_h   [Bv*Cv*HWv];

__device__ __forceinline__ float gelu_f(float v){
    float c = v + 0.044715f*v*v*v;
    float t = tanhf(0.7978845608028654f * c);
    return 0.5f*v*(1.f+t);
}

// ---------------- LayerNorm over channel dim, per (b,hw) ----------------
__global__ __launch_bounds__(256) void ln_kernel(const float* __restrict__ x,
        const float* __restrict__ w, const float* __restrict__ bias,
        float* __restrict__ out)
{
    int idx = blockIdx.x*blockDim.x + threadIdx.x;   // over Bv*HWv
    int b = idx / HWv, hw = idx % HWv;
    const float* xb = x + (size_t)b*Cv*HWv + hw;
    float s = 0.f, s2 = 0.f;
    #pragma unroll 8
    for (int c = 0; c < Cv; c++){ float v = xb[(size_t)c*HWv]; s += v; s2 += v*v; }
    float m   = s * (1.f/Cv);
    float var = s2 * (1.f/Cv) - m*m;
    float inv = rsqrtf(var + 1e-5f);
    float* ob = out + (size_t)b*Cv*HWv + hw;
    #pragma unroll 8
    for (int c = 0; c < Cv; c++){
        ob[(size_t)c*HWv] = (xb[(size_t)c*HWv] - m) * inv * w[c] + bias[c];
    }
}

// ---------------- generic SGEMM: out[b] = W(MxK) @ X[b](KxN) + epilogue ----------
// K = 256, N = 4096 always. M = gridDim.y*64. BM=64 BN=128 BK=16, 4x8 per thread.
__global__ __launch_bounds__(256) void sgemm_kernel(
    const float* __restrict__ Wt, const float* __restrict__ X, float* __restrict__ out,
    const float* __restrict__ bias, const float* __restrict__ resid, int act)
{
    __shared__ float Ws[64][17];
    __shared__ float Xs[16][128];
    int tid = threadIdx.x;
    int tx = tid & 15, ty = tid >> 4;
    int n0 = blockIdx.x * 128;
    int m0 = blockIdx.y * 64;
    int b  = blockIdx.z;
    int Mrows = gridDim.y * 64;
    const float* Xb = X + (size_t)b * Cv * HWv;

    float acc[4][8];
    #pragma unroll
    for (int i=0;i<4;i++)
        #pragma unroll
        for (int j=0;j<8;j++) acc[i][j] = 0.f;

    int wm  = tid >> 2;        // 0..63
    int wk4 = (tid & 3) * 4;   // 0,4,8,12

    for (int kt = 0; kt < 16; kt++){
        int k0 = kt * 16;
        float4 wv = *(const float4*)&Wt[(size_t)(m0 + wm) * Cv + k0 + wk4];
        Ws[wm][wk4+0] = wv.x; Ws[wm][wk4+1] = wv.y;
        Ws[wm][wk4+2] = wv.z; Ws[wm][wk4+3] = wv.w;
        #pragma unroll
        for (int e = 0; e < 2; e++){
            int lin = tid + e*256;          // 0..511 float4s
            int kr  = lin >> 5;             // 0..15
            int n4  = (lin & 31) * 4;       // 0..124
            float4 xv = *(const float4*)&Xb[(size_t)(k0+kr)*HWv + n0 + n4];
            *(float4*)&Xs[kr][n4] = xv;
        }
        __syncthreads();
        #pragma unroll
        for (int kk = 0; kk < 16; kk++){
            float a0 = Ws[ty*4+0][kk];
            float a1 = Ws[ty*4+1][kk];
            float a2 = Ws[ty*4+2][kk];
            float a3 = Ws[ty*4+3][kk];
            float4 x0 = *(const float4*)&Xs[kk][tx*4];
            float4 x1 = *(const float4*)&Xs[kk][tx*4+64];
            acc[0][0] += a0*x0.x; acc[0][1] += a0*x0.y; acc[0][2] += a0*x0.z; acc[0][3] += a0*x0.w;
            acc[1][0] += a1*x0.x; acc[1][1] += a1*x0.y; acc[1][2] += a1*x0.z; acc[1][3] += a1*x0.w;
            acc[2][0] += a2*x0.x; acc[2][1] += a2*x0.y; acc[2][2] += a2*x0.z; acc[2][3] += a2*x0.w;
            acc[3][0] += a3*x0.x; acc[3][1] += a3*x0.y; acc[3][2] += a3*x0.z; acc[3][3] += a3*x0.w;
            acc[0][4] += a0*x1.x; acc[0][5] += a0*x1.y; acc[0][6] += a0*x1.z; acc[0][7] += a0*x1.w;
            acc[1][4] += a1*x1.x; acc[1][5] += a1*x1.y; acc[1][6] += a1*x1.z; acc[1][7] += a1*x1.w;
            acc[2][4] += a2*x1.x; acc[2][5] += a2*x1.y; acc[2][6] += a2*x1.z; acc[2][7] += a2*x1.w;
            acc[3][4] += a3*x1.x; acc[3][5] += a3*x1.y; acc[3][6] += a3*x1.z; acc[3][7] += a3*x1.w;
        }
        __syncthreads();
    }

    #pragma unroll
    for (int i = 0; i < 4; i++){
        int m = m0 + ty*4 + i;
        float bv = bias ? bias[m] : 0.f;
        size_t obase = (size_t)b * Mrows * HWv + (size_t)m * HWv + n0;
        #pragma unroll
        for (int g = 0; g < 2; g++){
            int nc = tx*4 + g*64;
            float v0 = acc[i][g*4+0] + bv;
            float v1 = acc[i][g*4+1] + bv;
            float v2 = acc[i][g*4+2] + bv;
            float v3 = acc[i][g*4+3] + bv;
            if (act == 1){ v0 = gelu_f(v0); v1 = gelu_f(v1); v2 = gelu_f(v2); v3 = gelu_f(v3); }
            if (resid){
                const float* rp = resid + obase + nc;
                v0 += rp[0]; v1 += rp[1]; v2 += rp[2]; v3 += rp[3];
            }
            float4 r; r.x=v0; r.y=v1; r.z=v2; r.w=v3;
            *(float4*)&out[obase + nc] = r;
        }
    }
}

// ---------------- reciprocal L2 row norms (rows of length HW) ----------------
__global__ __launch_bounds__(256) void rownorm_kernel(const float* __restrict__ x,
        float* __restrict__ outinv, size_t batch_stride)
{
    int i  = blockIdx.x;
    int bb = i >> 8, c = i & 255;
    const float* p = x + (size_t)bb*batch_stride + (size_t)c*HWv;
    float s = 0.f;
    for (int h = threadIdx.x; h < HWv; h += 256){ float v = p[h]; s += v*v; }
    #pragma unroll
    for (int o = 16; o > 0; o >>= 1) s += __shfl_xor_sync(0xffffffffu, s, o);
    __shared__ float red[8];
    if ((threadIdx.x & 31) == 0) red[threadIdx.x >> 5] = s;
    __syncthreads();
    if (threadIdx.x == 0){
        float t = 0.f;
        #pragma unroll
        for (int w = 0; w < 8; w++) t += red[w];
        outinv[i] = 1.f / fmaxf(sqrtf(t), 1e-12f);
    }
}

// ---------------- split-K raw S = q @ k^T over HW=4096 (512 per split) ----------
__global__ __launch_bounds__(256) void attn_s_kernel()
{
    int split = blockIdx.x;        // 0..7
    int sn    = blockIdx.y;        // s*NHv + n
    int s = sn >> 2, n = sn & 3;
    int b = blockIdx.z;
    __shared__ float qs[32][65], ks[32][65];
    const float* qb = g_q  + ((size_t)b*Cv + n*HDv) * HWv;
    const float* kb = g_kv + ((size_t)(s*Bv + b)*2*Cv + n*HDv) * HWv;
    int tid = threadIdx.x;
    int tx = tid & 15, ty = tid >> 4;
    float acc[4][4];
    #pragma unroll
    for (int i=0;i<4;i++)
        #pragma unroll
        for (int j=0;j<4;j++) acc[i][j] = 0.f;

    for (int t = 0; t < 16; t++){
        int h0 = split*512 + t*32;
        #pragma unroll
        for (int e = 0; e < 8; e++){
            int lin = tid + e*256;
            int c = lin >> 5, hh = lin & 31;
            qs[hh][c] = qb[(size_t)c*HWv + h0 + hh];
            ks[hh][c] = kb[(size_t)c*HWv + h0 + hh];
        }
        __syncthreads();
        #pragma unroll
        for (int kk = 0; kk < 32; kk++){
            float a0 = qs[kk][ty*4+0], a1 = qs[kk][ty*4+1];
            float a2 = qs[kk][ty*4+2], a3 = qs[kk][ty*4+3];
            float b0 = ks[kk][tx*4+0], b1 = ks[kk][tx*4+1];
            float b2 = ks[kk][tx*4+2], b3 = ks[kk][tx*4+3];
            acc[0][0]+=a0*b0; acc[0][1]+=a0*b1; acc[0][2]+=a0*b2; acc[0][3]+=a0*b3;
            acc[1][0]+=a1*b0; acc[1][1]+=a1*b1; acc[1][2]+=a1*b2; acc[1][3]+=a1*b3;
            acc[2][0]+=a2*b0; acc[2][1]+=a2*b1; acc[2][2]+=a2*b2; acc[2][3]+=a2*b3;
            acc[3][0]+=a3*b0; acc[3][1]+=a3*b1; acc[3][2]+=a3*b2; acc[3][3]+=a3*b3;
        }
        __syncthreads();
    }
    float* op = g_spart + ((((size_t)split*2 + s)*Bv + b)*NHv + n) * 4096;
    #pragma unroll
    for (int i=0;i<4;i++)
        #pragma unroll
        for (int j=0;j<4;j++)
            op[(ty*4+i)*64 + tx*4 + j] = acc[i][j];
}

// ---------------- sum partials, scale by 1/(|q||k|), softmax, fold gate --------
__global__ void attn_softmax_kernel(const float* __restrict__ attn_scale)
{
    int n = blockIdx.x, b = blockIdx.y, s = blockIdx.z;
    __shared__ float S[64][65];
    int tid = threadIdx.x;  // 64 threads
    const float* qv = g_qinv + b*Cv + n*HDv;
    const float* kvv = g_kinv + (s*Bv + b)*Cv + n*HDv;
    size_t moff = (((size_t)s*Bv + b)*NHv + n) * 4096;
    for (int idx = tid; idx < 4096; idx += 64){
        int c = idx >> 6, d = idx & 63;
        float a = 0.f;
        #pragma unroll
        for (int sp = 0; sp < 8; sp++)
            a += g_spart[((((size_t)sp*2 + s)*Bv + b)*NHv + n)*4096 + idx];
        S[c][d] = a * qv[c] * kvv[d];
    }
    __syncthreads();
    int c = tid;
    float g = 1.f / (1.f + expf(-attn_scale[n]));
    float factor = (s == 0) ? g : (1.f - g);
    float mx = -1e30f;
    for (int d = 0; d < 64; d++) mx = fmaxf(mx, S[c][d]);
    float sum = 0.f;
    for (int d = 0; d < 64; d++){ float e = expf(S[c][d] - mx); S[c][d] = e; sum += e; }
    float r = factor / sum;
    float* op = g_attn + moff;
    for (int d = 0; d < 64; d++) op[c*64 + d] = S[c][d] * r;
}

// ---------------- qkv = Ptex@Vt + Pdep@Vd (gate already folded into P) ---------
#define AV_SMEM ((2*64*66 + 2*64*68)*4)
__global__ __launch_bounds__(256) void attn_av_kernel()
{
    extern __shared__ float sm[];
    float* Pt = sm;
    float* Pd = sm + 64*66;
    float* Vt = sm + 2*64*66;
    float* Vd = sm + 2*64*66 + 64*68;
    int hw0 = blockIdx.x * 64;
    int n = blockIdx.y, b = blockIdx.z;
    int tid = threadIdx.x, tx = tid & 15, ty = tid >> 4;
    const float* pt = g_attn + (((size_t)0*Bv + b)*NHv + n) * 4096;
    const float* pd = g_attn + (((size_t)1*Bv + b)*NHv + n) * 4096;
    const float* vt = g_kv + ((size_t)b*2*Cv + Cv + n*HDv) * HWv;
    const float* vd = g_kv + ((size_t)(Bv+b)*2*Cv + Cv + n*HDv) * HWv;
    #pragma unroll
    for (int e = 0; e < 16; e++){
        int lin = tid + e*256;          // 0..4095
        int r = lin >> 6, cc = lin & 63;
        Pt[r*66+cc] = pt[lin];
        Pd[r*66+cc] = pd[lin];
        Vt[r*68+cc] = vt[(size_t)r*HWv + hw0 + cc];
        Vd[r*68+cc] = vd[(size_t)r*HWv + hw0 + cc];
    }
    __syncthreads();
    float acc[4][4];
    #pragma unroll
    for (int i=0;i<4;i++)
        #pragma unroll
        for (int j=0;j<4;j++) acc[i][j] = 0.f;
    #pragma unroll 4
    for (int kk = 0; kk < 64; kk++){
        float at0 = Pt[(ty*4+0)*66+kk], at1 = Pt[(ty*4+1)*66+kk];
        float at2 = Pt[(ty*4+2)*66+kk], at3 = Pt[(ty*4+3)*66+kk];
        float ad0 = Pd[(ty*4+0)*66+kk], ad1 = Pd[(ty*4+1)*66+kk];
        float ad2 = Pd[(ty*4+2)*66+kk], ad3 = Pd[(ty*4+3)*66+kk];
        float4 bt = *(const float4*)&Vt[kk*68 + tx*4];
        float4 bd = *(const float4*)&Vd[kk*68 + tx*4];
        acc[0][0]+=at0*bt.x+ad0*bd.x; acc[0][1]+=at0*bt.y+ad0*bd.y;
        acc[0][2]+=at0*bt.z+ad0*bd.z; acc[0][3]+=at0*bt.w+ad0*bd.w;
        acc[1][0]+=at1*bt.x+ad1*bd.x; acc[1][1]+=at1*bt.y+ad1*bd.y;
        acc[1][2]+=at1*bt.z+ad1*bd.z; acc[1][3]+=at1*bt.w+ad1*bd.w;
        acc[2][0]+=at2*bt.x+ad2*bd.x; acc[2][1]+=at2*bt.y+ad2*bd.y;
        acc[2][2]+=at2*bt.z+ad2*bd.z; acc[2][3]+=at2*bt.w+ad2*bd.w;
        acc[3][0]+=at3*bt.x+ad3*bd.x; acc[3][1]+=at3*bt.y+ad3*bd.y;
        acc[3][2]+=at3*bt.z+ad3*bd.z; acc[3][3]+=at3*bt.w+ad3*bd.w;
    }
    float* op = g_qkv + ((size_t)b*Cv + n*HDv) * HWv + hw0;
    #pragma unroll
    for (int i=0;i<4;i++)
        #pragma unroll
        for (int j=0;j<4;j++)
            op[(size_t)(ty*4+i)*HWv + tx*4 + j] = acc[i][j];
}

// ---------------- host launcher ----------------
extern "C" void kernel_launch(void* const* d_in, const int* in_sizes, int n_in,
                              void* d_out, int out_size)
{
    const float* img    = (const float*)d_in[0];
    const float* aux0   = (const float*)d_in[1];
    const float* aux1   = (const float*)d_in[2];
    const float* qlnw   = (const float*)d_in[3];
    const float* qlnb   = (const float*)d_in[4];
    const float* kvlnw  = (const float*)d_in[5];
    const float* kvlnb  = (const float*)d_in[6];
    const float* Wq     = (const float*)d_in[7];
    const float* Wkv    = (const float*)d_in[8];
    const float* Wo     = (const float*)d_in[9];
    const float* bo     = (const float*)d_in[10];
    const float* ascale = (const float*)d_in[11];
    const float* mlnw   = (const float*)d_in[12];
    const float* mlnb   = (const float*)d_in[13];
    const float* W1     = (const float*)d_in[14];
    const float* b1     = (const float*)d_in[15];
    const float* W2     = (const float*)d_in[16];
    const float* b2     = (const float*)d_in[17];

    float *qln, *kvln, *qbuf, *kvbuf, *qinv, *kinv, *qkv, *xbuf, *yln, *hbuf;
    cudaGetSymbolAddress((void**)&qln,  g_qln);
    cudaGetSymbolAddress((void**)&kvln, g_kvln);
    cudaGetSymbolAddress((void**)&qbuf, g_q);
    cudaGetSymbolAddress((void**)&kvbuf,g_kv);
    cudaGetSymbolAddress((void**)&qinv, g_qinv);
    cudaGetSymbolAddress((void**)&kinv, g_kinv);
    cudaGetSymbolAddress((void**)&qkv,  g_qkv);
    cudaGetSymbolAddress((void**)&xbuf, g_x);
    cudaGetSymbolAddress((void**)&yln,  g_yln);
    cudaGetSymbolAddress((void**)&hbuf, g_h);

    cudaFuncSetAttribute(attn_av_kernel,
                         cudaFuncAttributeMaxDynamicSharedMemorySize, AV_SMEM);

    const int LNB = (Bv*HWv)/256;   // 128

    // 1. LayerNorms of inputs
    ln_kernel<<<LNB,256>>>(img,  qlnw,  qlnb,  qln);
    ln_kernel<<<LNB,256>>>(aux0, kvlnw, kvlnb, kvln);
    ln_kernel<<<LNB,256>>>(aux1, kvlnw, kvlnb, kvln + (size_t)Bv*Cv*HWv);

    // 2. Projections
    sgemm_kernel<<<dim3(32,4,Bv),   256>>>(Wq,  qln,  qbuf,  nullptr, nullptr, 0);
    sgemm_kernel<<<dim3(32,8,2*Bv), 256>>>(Wkv, kvln, kvbuf, nullptr, nullptr, 0);

    // 3. Reciprocal row norms of q and k
    rownorm_kernel<<<Bv*Cv,   256>>>(qbuf,  qinv, (size_t)Cv*HWv);
    rownorm_kernel<<<2*Bv*Cv, 256>>>(kvbuf, kinv, (size_t)2*Cv*HWv);

    // 4. Attention: raw S (split-K), softmax+gate, P@V
    attn_s_kernel      <<<dim3(8, 2*NHv, Bv), 256>>>();
    attn_softmax_kernel<<<dim3(NHv, Bv, 2),    64>>>(ascale);
    attn_av_kernel     <<<dim3(HWv/64, NHv, Bv), 256, AV_SMEM>>>();

    // 5. Output projection + residual:  x = img + Wo@qkv + bo
    sgemm_kernel<<<dim3(32,4,Bv), 256>>>(Wo, qkv, xbuf, bo, img, 0);

    // 6. MLP: LN, W1+gelu, W2 + residual -> out
    ln_kernel<<<LNB,256>>>(xbuf, mlnw, mlnb, yln);
    sgemm_kernel<<<dim3(32,4,Bv), 256>>>(W1, yln,  hbuf,           b1, nullptr, 1);
    sgemm_kernel<<<dim3(32,4,Bv), 256>>>(W2, hbuf, (float*)d_out,  b2, xbuf,   0);
}

// round 6
// speedup vs baseline: 1.4815x; 1.4815x over previous
#include <cuda_runtime.h>
#include <cuda_bf16.h>
#include <math.h>
#include <stdint.h>

#define Bv 8
#define Cv 256
#define HWv 4096
#define NHv 4
#define HDv 64

typedef __nv_bfloat16 bf16;

// ---------------- scratch (device globals; no allocations) ----------------
__device__ bf16 g_xa_h [Bv*HWv*Cv];        // XT activations (img-LN, later mlp-LN)
__device__ bf16 g_xa_l [Bv*HWv*Cv];
__device__ bf16 g_xkv_h[2*Bv*HWv*Cv];
__device__ bf16 g_xkv_l[2*Bv*HWv*Cv];
__device__ bf16 g_xqkv_h[Bv*HWv*Cv];
__device__ bf16 g_xqkv_l[Bv*HWv*Cv];
__device__ bf16 g_xh_h [Bv*HWv*Cv];
__device__ bf16 g_xh_l [Bv*HWv*Cv];
__device__ bf16 g_w_h[393216];             // Wq|Wkv|Wo|W1|W2 hi
__device__ bf16 g_w_l[393216];             // lo
__device__ float g_q  [Bv*Cv*HWv];
__device__ float g_kv [2*Bv*2*Cv*HWv];
__device__ float g_x  [Bv*Cv*HWv];
__device__ float g_qinv[Bv*Cv];
__device__ float g_kinv[2*Bv*Cv];
__device__ float g_spart[8*2*Bv*NHv*HDv*HDv];
__device__ float g_attn [2*Bv*NHv*HDv*HDv];

// ---------------- helpers ----------------
__device__ __forceinline__ uint32_t smem_to_u32(const void* p){
    uint32_t a;
    asm("{ .reg .u64 t; cvta.to.shared.u64 t, %1; cvt.u32.u64 %0, t; }" : "=r"(a) : "l"(p));
    return a;
}
__device__ __forceinline__ void ldmatrix_x4(uint32_t* r, uint32_t addr){
    asm volatile("ldmatrix.sync.aligned.m8n8.x4.shared.b16 {%0,%1,%2,%3}, [%4];"
        : "=r"(r[0]), "=r"(r[1]), "=r"(r[2]), "=r"(r[3]) : "r"(addr));
}
__device__ __forceinline__ void mma_bf16(float* d, const uint32_t* a, uint32_t b0, uint32_t b1){
    asm volatile("mma.sync.aligned.m16n8k16.row.col.f32.bf16.bf16.f32 "
        "{%0,%1,%2,%3}, {%4,%5,%6,%7}, {%8,%9}, {%0,%1,%2,%3};"
        : "+f"(d[0]), "+f"(d[1]), "+f"(d[2]), "+f"(d[3])
        : "r"(a[0]), "r"(a[1]), "r"(a[2]), "r"(a[3]), "r"(b0), "r"(b1));
}
__device__ __forceinline__ float gelu_f(float v){
    float c = v + 0.044715f*v*v*v;
    float t = tanhf(0.7978845608028654f * c);
    return 0.5f*v*(1.f+t);
}
__device__ __forceinline__ void split_bf16(float v, bf16& h, bf16& l){
    h = __float2bfloat16(v);
    l = __float2bfloat16(v - __bfloat162float(h));
}

// ---------------- weight fp32 -> bf16 hi/lo ----------------
__global__ void wconv_kernel(const float* __restrict__ w, bf16* __restrict__ h,
                             bf16* __restrict__ l, int n){
    int i = blockIdx.x*256 + threadIdx.x;
    if (i < n){ bf16 hh, ll; split_bf16(w[i], hh, ll); h[i] = hh; l[i] = ll; }
}

// ---------------- LayerNorm over C -> transposed bf16 hi/lo [b][hw][c] ----------
__global__ __launch_bounds__(256) void ln_xt_kernel(const float* __restrict__ x,
        const float* __restrict__ w, const float* __restrict__ bias,
        bf16* __restrict__ oh, bf16* __restrict__ ol)
{
    int idx = blockIdx.x*blockDim.x + threadIdx.x;
    int b = idx / HWv, hw = idx % HWv;
    const float* xb = x + (size_t)b*Cv*HWv + hw;
    float s = 0.f, s2 = 0.f;
    #pragma unroll 8
    for (int c = 0; c < Cv; c++){ float v = xb[(size_t)c*HWv]; s += v; s2 += v*v; }
    float m   = s * (1.f/Cv);
    float var = s2 * (1.f/Cv) - m*m;
    float inv = rsqrtf(var + 1e-5f);
    size_t base = ((size_t)b*HWv + hw) * Cv;
    for (int c8 = 0; c8 < Cv/8; c8++){
        uint4 hp, lp;
        bf16* hh = (bf16*)&hp; bf16* ll = (bf16*)&lp;
        #pragma unroll
        for (int i = 0; i < 8; i++){
            int c = c8*8 + i;
            float v = (xb[(size_t)c*HWv] - m) * inv * w[c] + bias[c];
            split_bf16(v, hh[i], ll[i]);
        }
        *(uint4*)&oh[base + c8*8] = hp;
        *(uint4*)&ol[base + c8*8] = lp;
    }
}

// ---------------- HMMA bf16x3 GEMM: D[m,n] = W[m,:] . XT[n,:] --------------------
// A = W (K-major [M][256] hi/lo), B = XT (K-major [b][4096][256] hi/lo)
// CTA 128x128, 8 warps (4 m x 2 n), warp tile 32x64. K staged 64 at a time.
// mode 0: out fp32 [b][M][4096]
// mode 1: oxh/oxl bf16 XT [b][4096][256], +bias, gelu
// mode 2: out fp32, +bias +resid
#define RS 72                         // smem row stride in bf16 (144 B)
#define OFF_AH 0
#define OFF_AL 18432
#define OFF_BH 36864
#define OFF_BL 55296
#define GEMM_SMEM 73728

__global__ __launch_bounds__(256,2) void gemm_kernel(
    const bf16* __restrict__ Ah, const bf16* __restrict__ Al,
    const bf16* __restrict__ Bh, const bf16* __restrict__ Bl,
    float* __restrict__ out, bf16* __restrict__ oxh, bf16* __restrict__ oxl,
    const float* __restrict__ bias, const float* __restrict__ resid,
    int mode, int Mrows)
{
    extern __shared__ char sm[];
    uint32_t smb = smem_to_u32(sm);
    int tid = threadIdx.x, lane = tid & 31, warp = tid >> 5;
    int warp_m = warp & 3, warp_n = warp >> 2;
    int n0 = blockIdx.x*128, m0 = blockIdx.y*128, b = blockIdx.z;
    const bf16* Bhb = Bh + (size_t)b*HWv*Cv;
    const bf16* Blb = Bl + (size_t)b*HWv*Cv;

    float d[2][8][4];
    #pragma unroll
    for (int i=0;i<2;i++)
        #pragma unroll
        for (int j=0;j<8;j++)
            #pragma unroll
            for (int k=0;k<4;k++) d[i][j][k] = 0.f;

    // precomputed ldmatrix lane address components
    int a_row = (lane & 7) + ((lane >> 3) & 1) * 8;     // row within 16
    int a_kc  = (lane >> 4) * 8;                        // 0 or 8
    int b_row = (lane & 7) + (lane >> 4) * 8;           // n within 16
    int b_kc  = ((lane >> 3) & 1) * 8;                  // 0 or 8

    for (int kt = 0; kt < 4; kt++){
        int k0 = kt*64;
        #pragma unroll
        for (int it = 0; it < 4; it++){
            int lin = tid + it*256;            // 0..1023
            int row = lin >> 3, kk = lin & 7;
            uint32_t so = row*(RS*2) + kk*16;
            size_t ga = (size_t)(m0+row)*Cv + k0 + kk*8;
            size_t gb = (size_t)(n0+row)*Cv + k0 + kk*8;
            *(uint4*)(sm+OFF_AH+so) = *(const uint4*)(Ah +ga);
            *(uint4*)(sm+OFF_AL+so) = *(const uint4*)(Al +ga);
            *(uint4*)(sm+OFF_BH+so) = *(const uint4*)(Bhb+gb);
            *(uint4*)(sm+OFF_BL+so) = *(const uint4*)(Blb+gb);
        }
        __syncthreads();
        #pragma unroll
        for (int k16 = 0; k16 < 4; k16++){
            uint32_t ah[2][4], al[2][4];
            #pragma unroll
            for (int fm = 0; fm < 2; fm++){
                int arow = warp_m*32 + fm*16 + a_row;
                uint32_t aaddr = smb + OFF_AH + arow*(RS*2) + (k16*16 + a_kc)*2;
                ldmatrix_x4(ah[fm], aaddr);
                ldmatrix_x4(al[fm], aaddr + (OFF_AL-OFF_AH));
            }
            #pragma unroll
            for (int half = 0; half < 2; half++){
                uint32_t bh[2][4], bl[2][4];
                #pragma unroll
                for (int p = 0; p < 2; p++){
                    int nrow = warp_n*64 + half*32 + p*16 + b_row;
                    uint32_t baddr = smb + OFF_BH + nrow*(RS*2) + (k16*16 + b_kc)*2;
                    ldmatrix_x4(bh[p], baddr);
                    ldmatrix_x4(bl[p], baddr + (OFF_BL-OFF_BH));
                }
                #pragma unroll
                for (int fm = 0; fm < 2; fm++)
                    #pragma unroll
                    for (int j = 0; j < 4; j++){
                        float* dd = d[fm][half*4+j];
                        uint32_t* fh = &bh[j>>1][(j&1)*2];
                        uint32_t* fl = &bl[j>>1][(j&1)*2];
                        mma_bf16(dd, ah[fm], fh[0], fh[1]);   // Ah*Bh
                        mma_bf16(dd, ah[fm], fl[0], fl[1]);   // Ah*Bl
                        mma_bf16(dd, al[fm], fh[0], fh[1]);   // Al*Bh
                    }
            }
        }
        __syncthreads();
    }

    // stage D (128x128 fp32) through smem for coalesced / transposed output
    float* stage = (float*)sm;            // [128][132]
    #pragma unroll
    for (int fm = 0; fm < 2; fm++)
        #pragma unroll
        for (int fn = 0; fn < 8; fn++){
            int row = warp_m*32 + fm*16 + (lane>>2);
            int col = warp_n*64 + fn*8 + 2*(lane&3);
            *(float2*)&stage[row*132+col]     = make_float2(d[fm][fn][0], d[fm][fn][1]);
            *(float2*)&stage[(row+8)*132+col] = make_float2(d[fm][fn][2], d[fm][fn][3]);
        }
    __syncthreads();

    if (mode != 1){
        int col = tid & 127, mr0 = tid >> 7;
        #pragma unroll 8
        for (int it = 0; it < 64; it++){
            int m = it*2 + mr0;
            float v = stage[m*132 + col];
            size_t o = ((size_t)b*Mrows + m0 + m)*HWv + n0 + col;
            if (mode == 2) v += bias[m0+m] + resid[o];
            out[o] = v;
        }
    } else {
        int n = tid >> 1;
        int mh = (tid & 1) * 64;
        size_t ro = ((size_t)b*HWv + n0 + n)*Cv + m0 + mh;
        #pragma unroll
        for (int c8 = 0; c8 < 8; c8++){
            uint4 hp, lp;
            bf16* hh = (bf16*)&hp; bf16* ll = (bf16*)&lp;
            #pragma unroll
            for (int i = 0; i < 8; i++){
                int m = mh + c8*8 + i;
                float v = gelu_f(stage[m*132 + n] + bias[m0 + m]);
                split_bf16(v, hh[i], ll[i]);
            }
            *(uint4*)&oxh[ro + c8*8] = hp;
            *(uint4*)&oxl[ro + c8*8] = lp;
        }
    }
}

// ---------------- reciprocal L2 row norms ----------------
__global__ __launch_bounds__(256) void rownorm_kernel(const float* __restrict__ x,
        float* __restrict__ outinv, size_t batch_stride)
{
    int i  = blockIdx.x;
    int bb = i >> 8, c = i & 255;
    const float* p = x + (size_t)bb*batch_stride + (size_t)c*HWv;
    float s = 0.f;
    for (int h = threadIdx.x; h < HWv; h += 256){ float v = p[h]; s += v*v; }
    #pragma unroll
    for (int o = 16; o > 0; o >>= 1) s += __shfl_xor_sync(0xffffffffu, s, o);
    __shared__ float red[8];
    if ((threadIdx.x & 31) == 0) red[threadIdx.x >> 5] = s;
    __syncthreads();
    if (threadIdx.x == 0){
        float t = 0.f;
        #pragma unroll
        for (int w = 0; w < 8; w++) t += red[w];
        outinv[i] = 1.f / fmaxf(sqrtf(t), 1e-12f);
    }
}

// ---------------- split-K raw S = q @ k^T over HW ----------------
__global__ __launch_bounds__(256) void attn_s_kernel()
{
    int split = blockIdx.x;
    int sn    = blockIdx.y;
    int s = sn >> 2, n = sn & 3;
    int b = blockIdx.z;
    __shared__ float qs[32][65], ks[32][65];
    const float* qb = g_q  + ((size_t)b*Cv + n*HDv) * HWv;
    const float* kb = g_kv + ((size_t)(s*Bv + b)*2*Cv + n*HDv) * HWv;
    int tid = threadIdx.x;
    int tx = tid & 15, ty = tid >> 4;
    float acc[4][4];
    #pragma unroll
    for (int i=0;i<4;i++)
        #pragma unroll
        for (int j=0;j<4;j++) acc[i][j] = 0.f;

    for (int t = 0; t < 16; t++){
        int h0 = split*512 + t*32;
        #pragma unroll
        for (int e = 0; e < 8; e++){
            int lin = tid + e*256;
            int c = lin >> 5, hh = lin & 31;
            qs[hh][c] = qb[(size_t)c*HWv + h0 + hh];
            ks[hh][c] = kb[(size_t)c*HWv + h0 + hh];
        }
        __syncthreads();
        #pragma unroll
        for (int kk = 0; kk < 32; kk++){
            float a0 = qs[kk][ty*4+0], a1 = qs[kk][ty*4+1];
            float a2 = qs[kk][ty*4+2], a3 = qs[kk][ty*4+3];
            float b0 = ks[kk][tx*4+0], b1 = ks[kk][tx*4+1];
            float b2 = ks[kk][tx*4+2], b3 = ks[kk][tx*4+3];
            acc[0][0]+=a0*b0; acc[0][1]+=a0*b1; acc[0][2]+=a0*b2; acc[0][3]+=a0*b3;
            acc[1][0]+=a1*b0; acc[1][1]+=a1*b1; acc[1][2]+=a1*b2; acc[1][3]+=a1*b3;
            acc[2][0]+=a2*b0; acc[2][1]+=a2*b1; acc[2][2]+=a2*b2; acc[2][3]+=a2*b3;
            acc[3][0]+=a3*b0; acc[3][1]+=a3*b1; acc[3][2]+=a3*b2; acc[3][3]+=a3*b3;
        }
        __syncthreads();
    }
    float* op = g_spart + ((((size_t)split*2 + s)*Bv + b)*NHv + n) * 4096;
    #pragma unroll
    for (int i=0;i<4;i++)
        #pragma unroll
        for (int j=0;j<4;j++)
            op[(ty*4+i)*64 + tx*4 + j] = acc[i][j];
}

// ---------------- sum partials, scale, softmax, fold gate ----------------
__global__ void attn_softmax_kernel(const float* __restrict__ attn_scale)
{
    int n = blockIdx.x, b = blockIdx.y, s = blockIdx.z;
    __shared__ float S[64][65];
    int tid = threadIdx.x;
    const float* qv  = g_qinv + b*Cv + n*HDv;
    const float* kvv = g_kinv + (s*Bv + b)*Cv + n*HDv;
    size_t moff = (((size_t)s*Bv + b)*NHv + n) * 4096;
    for (int idx = tid; idx < 4096; idx += 64){
        int c = idx >> 6, d = idx & 63;
        float a = 0.f;
        #pragma unroll
        for (int sp = 0; sp < 8; sp++)
            a += g_spart[((((size_t)sp*2 + s)*Bv + b)*NHv + n)*4096 + idx];
        S[c][d] = a * qv[c] * kvv[d];
    }
    __syncthreads();
    int c = tid;
    float g = 1.f / (1.f + expf(-attn_scale[n]));
    float factor = (s == 0) ? g : (1.f - g);
    float mx = -1e30f;
    for (int d = 0; d < 64; d++) mx = fmaxf(mx, S[c][d]);
    float sum = 0.f;
    for (int d = 0; d < 64; d++){ float e = expf(S[c][d] - mx); S[c][d] = e; sum += e; }
    float r = factor / sum;
    float* op = g_attn + moff;
    for (int d = 0; d < 64; d++) op[c*64 + d] = S[c][d] * r;
}

// ---------------- qkv = Ptex@Vt + Pdep@Vd -> transposed bf16 hi/lo XT ------------
#define AV_SMEM ((2*64*66 + 2*64*68)*4)
__global__ __launch_bounds__(256) void attn_av_kernel()
{
    extern __shared__ char smc[];
    float* smf = (float*)smc;
    float* Pt = smf;
    float* Pd = smf + 64*66;
    float* Vt = smf + 2*64*66;
    float* Vd = smf + 2*64*66 + 64*68;
    int hw0 = blockIdx.x * 64;
    int n = blockIdx.y, b = blockIdx.z;
    int tid = threadIdx.x, tx = tid & 15, ty = tid >> 4;
    const float* pt = g_attn + (((size_t)0*Bv + b)*NHv + n) * 4096;
    const float* pd = g_attn + (((size_t)1*Bv + b)*NHv + n) * 4096;
    const float* vt = g_kv + ((size_t)b*2*Cv + Cv + n*HDv) * HWv;
    const float* vd = g_kv + ((size_t)(Bv+b)*2*Cv + Cv + n*HDv) * HWv;
    #pragma unroll
    for (int e = 0; e < 16; e++){
        int lin = tid + e*256;
        int r = lin >> 6, cc = lin & 63;
        Pt[r*66+cc] = pt[lin];
        Pd[r*66+cc] = pd[lin];
        Vt[r*68+cc] = vt[(size_t)r*HWv + hw0 + cc];
        Vd[r*68+cc] = vd[(size_t)r*HWv + hw0 + cc];
    }
    __syncthreads();
    float acc[4][4];
    #pragma unroll
    for (int i=0;i<4;i++)
        #pragma unroll
        for (int j=0;j<4;j++) acc[i][j] = 0.f;
    #pragma unroll 4
    for (int kk = 0; kk < 64; kk++){
        float at0 = Pt[(ty*4+0)*66+kk], at1 = Pt[(ty*4+1)*66+kk];
        float at2 = Pt[(ty*4+2)*66+kk], at3 = Pt[(ty*4+3)*66+kk];
        float ad0 = Pd[(ty*4+0)*66+kk], ad1 = Pd[(ty*4+1)*66+kk];
        float ad2 = Pd[(ty*4+2)*66+kk], ad3 = Pd[(ty*4+3)*66+kk];
        float4 bt = *(const float4*)&Vt[kk*68 + tx*4];
        float4 bd = *(const float4*)&Vd[kk*68 + tx*4];
        acc[0][0]+=at0*bt.x+ad0*bd.x; acc[0][1]+=at0*bt.y+ad0*bd.y;
        acc[0][2]+=at0*bt.z+ad0*bd.z; acc[0][3]+=at0*bt.w+ad0*bd.w;
        acc[1][0]+=at1*bt.x+ad1*bd.x; acc[1][1]+=at1*bt.y+ad1*bd.y;
        acc[1][2]+=at1*bt.z+ad1*bd.z; acc[1][3]+=at1*bt.w+ad1*bd.w;
        acc[2][0]+=at2*bt.x+ad2*bd.x; acc[2][1]+=at2*bt.y+ad2*bd.y;
        acc[2][2]+=at2*bt.z+ad2*bd.z; acc[2][3]+=at2*bt.w+ad2*bd.w;
        acc[3][0]+=at3*bt.x+ad3*bd.x; acc[3][1]+=at3*bt.y+ad3*bd.y;
        acc[3][2]+=at3*bt.z+ad3*bd.z; acc[3][3]+=at3*bt.w+ad3*bd.w;
    }
    // transpose in smem (reuse Pt), then write qkv^T as bf16 hi/lo
    __syncthreads();
    #pragma unroll
    for (int i=0;i<4;i++)
        #pragma unroll
        for (int j=0;j<4;j++)
            Pt[(tx*4+j)*66 + ty*4+i] = acc[i][j];
    __syncthreads();
    int hw_l = tid >> 2;          // 0..63
    int cq   = (tid & 3) * 16;    // 0,16,32,48
    uint4 hp[2], lp[2];
    bf16* hh = (bf16*)hp; bf16* ll = (bf16*)lp;
    #pragma unroll
    for (int i = 0; i < 16; i++){
        float v = Pt[hw_l*66 + cq + i];
        split_bf16(v, hh[i], ll[i]);
    }
    size_t ro = ((size_t)b*HWv + hw0 + hw_l)*Cv + n*HDv + cq;
    *(uint4*)&g_xqkv_h[ro]   = hp[0];
    *(uint4*)&g_xqkv_h[ro+8] = hp[1];
    *(uint4*)&g_xqkv_l[ro]   = lp[0];
    *(uint4*)&g_xqkv_l[ro+8] = lp[1];
}

// ---------------- host launcher ----------------
extern "C" void kernel_launch(void* const* d_in, const int* in_sizes, int n_in,
                              void* d_out, int out_size)
{
    const float* img    = (const float*)d_in[0];
    const float* aux0   = (const float*)d_in[1];
    const float* aux1   = (const float*)d_in[2];
    const float* qlnw   = (const float*)d_in[3];
    const float* qlnb   = (const float*)d_in[4];
    const float* kvlnw  = (const float*)d_in[5];
    const float* kvlnb  = (const float*)d_in[6];
    const float* Wq     = (const float*)d_in[7];
    const float* Wkv    = (const float*)d_in[8];
    const float* Wo     = (const float*)d_in[9];
    const float* bo     = (const float*)d_in[10];
    const float* ascale = (const float*)d_in[11];
    const float* mlnw   = (const float*)d_in[12];
    const float* mlnb   = (const float*)d_in[13];
    const float* W1     = (const float*)d_in[14];
    const float* b1     = (const float*)d_in[15];
    const float* W2     = (const float*)d_in[16];
    const float* b2     = (const float*)d_in[17];

    bf16 *xa_h,*xa_l,*xkv_h,*xkv_l,*xqkv_h,*xqkv_l,*xh_h,*xh_l,*wh,*wl;
    float *qbuf,*kvbuf,*xbuf,*qinv,*kinv;
    cudaGetSymbolAddress((void**)&xa_h,  g_xa_h);
    cudaGetSymbolAddress((void**)&xa_l,  g_xa_l);
    cudaGetSymbolAddress((void**)&xkv_h, g_xkv_h);
    cudaGetSymbolAddress((void**)&xkv_l, g_xkv_l);
    cudaGetSymbolAddress((void**)&xqkv_h,g_xqkv_h);
    cudaGetSymbolAddress((void**)&xqkv_l,g_xqkv_l);
    cudaGetSymbolAddress((void**)&xh_h,  g_xh_h);
    cudaGetSymbolAddress((void**)&xh_l,  g_xh_l);
    cudaGetSymbolAddress((void**)&wh,    g_w_h);
    cudaGetSymbolAddress((void**)&wl,    g_w_l);
    cudaGetSymbolAddress((void**)&qbuf,  g_q);
    cudaGetSymbolAddress((void**)&kvbuf, g_kv);
    cudaGetSymbolAddress((void**)&xbuf,  g_x);
    cudaGetSymbolAddress((void**)&qinv,  g_qinv);
    cudaGetSymbolAddress((void**)&kinv,  g_kinv);

    cudaFuncSetAttribute(gemm_kernel,
                         cudaFuncAttributeMaxDynamicSharedMemorySize, GEMM_SMEM);
    cudaFuncSetAttribute(attn_av_kernel,
                         cudaFuncAttributeMaxDynamicSharedMemorySize, AV_SMEM);

    // weight offsets within g_w_h/g_w_l
    const int WQ_O = 0, WKV_O = 65536, WO_O = 196608, W1_O = 262144, W2_O = 327680;

    // 0. weight conversion (tiny)
    wconv_kernel<<<256,256>>>(Wq,  wh+WQ_O,  wl+WQ_O,  65536);
    wconv_kernel<<<512,256>>>(Wkv, wh+WKV_O, wl+WKV_O, 131072);
    wconv_kernel<<<256,256>>>(Wo,  wh+WO_O,  wl+WO_O,  65536);
    wconv_kernel<<<256,256>>>(W1,  wh+W1_O,  wl+W1_O,  65536);
    wconv_kernel<<<256,256>>>(W2,  wh+W2_O,  wl+W2_O,  65536);

    const int LNB = (Bv*HWv)/256;   // 128

    // 1. LayerNorms -> transposed bf16 hi/lo activations
    ln_xt_kernel<<<LNB,256>>>(img,  qlnw,  qlnb,  xa_h,  xa_l);
    ln_xt_kernel<<<LNB,256>>>(aux0, kvlnw, kvlnb, xkv_h, xkv_l);
    ln_xt_kernel<<<LNB,256>>>(aux1, kvlnw, kvlnb,
                              xkv_h + (size_t)Bv*HWv*Cv, xkv_l + (size_t)Bv*HWv*Cv);

    // 2. Projections (HMMA bf16x3)
    gemm_kernel<<<dim3(32,2,Bv),   256, GEMM_SMEM>>>(wh+WQ_O,  wl+WQ_O,  xa_h,  xa_l,
        qbuf,  nullptr, nullptr, nullptr, nullptr, 0, 256);
    gemm_kernel<<<dim3(32,4,2*Bv), 256, GEMM_SMEM>>>(wh+WKV_O, wl+WKV_O, xkv_h, xkv_l,
        kvbuf, nullptr, nullptr, nullptr, nullptr, 0, 512);

    // 3. Reciprocal row norms
    rownorm_kernel<<<Bv*Cv,   256>>>(qbuf,  qinv, (size_t)Cv*HWv);
    rownorm_kernel<<<2*Bv*Cv, 256>>>(kvbuf, kinv, (size_t)2*Cv*HWv);

    // 4. Attention
    attn_s_kernel      <<<dim3(8, 2*NHv, Bv), 256>>>();
    attn_softmax_kernel<<<dim3(NHv, Bv, 2),    64>>>(ascale);
    attn_av_kernel     <<<dim3(HWv/64, NHv, Bv), 256, AV_SMEM>>>();

    // 5. x = img + Wo@qkv + bo
    gemm_kernel<<<dim3(32,2,Bv), 256, GEMM_SMEM>>>(wh+WO_O, wl+WO_O, xqkv_h, xqkv_l,
        xbuf, nullptr, nullptr, bo, img, 2, 256);

    // 6. MLP
    ln_xt_kernel<<<LNB,256>>>(xbuf, mlnw, mlnb, xa_h, xa_l);
    gemm_kernel<<<dim3(32,2,Bv), 256, GEMM_SMEM>>>(wh+W1_O, wl+W1_O, xa_h, xa_l,
        nullptr, xh_h, xh_l, b1, nullptr, 1, 256);
    gemm_kernel<<<dim3(32,2,Bv), 256, GEMM_SMEM>>>(wh+W2_O, wl+W2_O, xh_h, xh_l,
        (float*)d_out, nullptr, nullptr, b2, xbuf, 2, 256);
}

// round 7
// speedup vs baseline: 1.6362x; 1.1044x over previous
#include <cuda_runtime.h>
#include <cuda_bf16.h>
#include <math.h>
#include <stdint.h>

#define Bv 8
#define Cv 256
#define HWv 4096
#define NHv 4
#define HDv 64

typedef __nv_bfloat16 bf16;

// ---------------- scratch (device globals; no allocations) ----------------
__device__ bf16 g_xa_h [Bv*HWv*Cv];
__device__ bf16 g_xa_l [Bv*HWv*Cv];
__device__ bf16 g_xkv_h[2*Bv*HWv*Cv];
__device__ bf16 g_xkv_l[2*Bv*HWv*Cv];
__device__ bf16 g_xqkv_h[Bv*HWv*Cv];
__device__ bf16 g_xqkv_l[Bv*HWv*Cv];
__device__ bf16 g_xh_h [Bv*HWv*Cv];
__device__ bf16 g_xh_l [Bv*HWv*Cv];
__device__ bf16 g_w_h[393216];
__device__ bf16 g_w_l[393216];
__device__ bf16 g_qb_h[Bv*Cv*HWv];         // q K-major [b][c][hw]
__device__ bf16 g_qb_l[Bv*Cv*HWv];
__device__ bf16 g_kb_h[2*Bv*Cv*HWv];       // k K-major [sb][c][hw]
__device__ bf16 g_kb_l[2*Bv*Cv*HWv];
__device__ bf16 g_vt_h[2*Bv*HWv*Cv];       // v transposed [sb][hw][c]
__device__ bf16 g_vt_l[2*Bv*HWv*Cv];
__device__ bf16 g_ph[2*Bv*NHv*HDv*HDv];    // gated softmax(P) hi
__device__ bf16 g_pl[2*Bv*NHv*HDv*HDv];    // lo
__device__ float g_x  [Bv*Cv*HWv];
__device__ float g_qinv[Bv*Cv];
__device__ float g_kinv[2*Bv*Cv];
__device__ float g_spart[4*2*Bv*NHv*HDv*HDv];

// ---------------- helpers ----------------
__device__ __forceinline__ uint32_t smem_to_u32(const void* p){
    uint32_t a;
    asm("{ .reg .u64 t; cvta.to.shared.u64 t, %1; cvt.u32.u64 %0, t; }" : "=r"(a) : "l"(p));
    return a;
}
__device__ __forceinline__ void ldmatrix_x4(uint32_t* r, uint32_t addr){
    asm volatile("ldmatrix.sync.aligned.m8n8.x4.shared.b16 {%0,%1,%2,%3}, [%4];"
        : "=r"(r[0]), "=r"(r[1]), "=r"(r[2]), "=r"(r[3]) : "r"(addr));
}
__device__ __forceinline__ void mma_bf16(float* d, const uint32_t* a, uint32_t b0, uint32_t b1){
    asm volatile("mma.sync.aligned.m16n8k16.row.col.f32.bf16.bf16.f32 "
        "{%0,%1,%2,%3}, {%4,%5,%6,%7}, {%8,%9}, {%0,%1,%2,%3};"
        : "+f"(d[0]), "+f"(d[1]), "+f"(d[2]), "+f"(d[3])
        : "r"(a[0]), "r"(a[1]), "r"(a[2]), "r"(a[3]), "r"(b0), "r"(b1));
}
__device__ __forceinline__ float gelu_f(float v){
    float c = v + 0.044715f*v*v*v;
    float t = tanhf(0.7978845608028654f * c);
    return 0.5f*v*(1.f+t);
}
__device__ __forceinline__ void split_bf16(float v, bf16& h, bf16& l){
    h = __float2bfloat16(v);
    l = __float2bfloat16(v - __bfloat162float(h));
}

// ---------------- weight fp32 -> bf16 hi/lo ----------------
__global__ void wconv_kernel(const float* __restrict__ w, bf16* __restrict__ h,
                             bf16* __restrict__ l, int n){
    int i = blockIdx.x*256 + threadIdx.x;
    if (i < n){ bf16 hh, ll; split_bf16(w[i], hh, ll); h[i] = hh; l[i] = ll; }
}

// ---------------- LayerNorm over C -> transposed bf16 hi/lo [b][hw][c] ----------
__global__ __launch_bounds__(256) void ln_xt_kernel(const float* __restrict__ x,
        const float* __restrict__ w, const float* __restrict__ bias,
        bf16* __restrict__ oh, bf16* __restrict__ ol)
{
    int idx = blockIdx.x*blockDim.x + threadIdx.x;
    int b = idx / HWv, hw = idx % HWv;
    const float* xb = x + (size_t)b*Cv*HWv + hw;
    float s = 0.f, s2 = 0.f;
    #pragma unroll 8
    for (int c = 0; c < Cv; c++){ float v = xb[(size_t)c*HWv]; s += v; s2 += v*v; }
    float m   = s * (1.f/Cv);
    float var = s2 * (1.f/Cv) - m*m;
    float inv = rsqrtf(var + 1e-5f);
    size_t base = ((size_t)b*HWv + hw) * Cv;
    for (int c8 = 0; c8 < Cv/8; c8++){
        uint4 hp, lp;
        bf16* hh = (bf16*)&hp; bf16* ll = (bf16*)&lp;
        #pragma unroll
        for (int i = 0; i < 8; i++){
            int c = c8*8 + i;
            float v = (xb[(size_t)c*HWv] - m) * inv * w[c] + bias[c];
            split_bf16(v, hh[i], ll[i]);
        }
        *(uint4*)&oh[base + c8*8] = hp;
        *(uint4*)&ol[base + c8*8] = lp;
    }
}

// ---------------- HMMA bf16x3 GEMM: D[m,n] = W[m,:] . XT[n,:] --------------------
// mode 0: out fp32
// mode 1: oxh/oxl bf16 XT [b][hw][c], +bias, gelu
// mode 2: out fp32, +bias +resid
// mode 3: oxh/oxl bf16 K-major [b][Mrows][hw]   (q projection)
// mode 4: m<256 -> K-major kb (oxh/oxl); m>=256 -> XT vt (oxh2/oxl2)
#define RS 72
#define OFF_AH 0
#define OFF_AL 18432
#define OFF_BH 36864
#define OFF_BL 55296
#define GEMM_SMEM 73728

__global__ __launch_bounds__(256,2) void gemm_kernel(
    const bf16* __restrict__ Ah, const bf16* __restrict__ Al,
    const bf16* __restrict__ Bh, const bf16* __restrict__ Bl,
    float* __restrict__ out, bf16* __restrict__ oxh, bf16* __restrict__ oxl,
    bf16* __restrict__ oxh2, bf16* __restrict__ oxl2,
    const float* __restrict__ bias, const float* __restrict__ resid,
    int mode, int Mrows)
{
    extern __shared__ char sm[];
    uint32_t smb = smem_to_u32(sm);
    int tid = threadIdx.x, lane = tid & 31, warp = tid >> 5;
    int warp_m = warp & 3, warp_n = warp >> 2;
    int n0 = blockIdx.x*128, m0 = blockIdx.y*128, b = blockIdx.z;
    const bf16* Bhb = Bh + (size_t)b*HWv*Cv;
    const bf16* Blb = Bl + (size_t)b*HWv*Cv;

    float d[2][8][4];
    #pragma unroll
    for (int i=0;i<2;i++)
        #pragma unroll
        for (int j=0;j<8;j++)
            #pragma unroll
            for (int k=0;k<4;k++) d[i][j][k] = 0.f;

    int a_row = (lane & 7) + ((lane >> 3) & 1) * 8;
    int a_kc  = (lane >> 4) * 8;
    int b_row = (lane & 7) + (lane >> 4) * 8;
    int b_kc  = ((lane >> 3) & 1) * 8;

    for (int kt = 0; kt < 4; kt++){
        int k0 = kt*64;
        #pragma unroll
        for (int it = 0; it < 4; it++){
            int lin = tid + it*256;
            int row = lin >> 3, kk = lin & 7;
            uint32_t so = row*(RS*2) + kk*16;
            size_t ga = (size_t)(m0+row)*Cv + k0 + kk*8;
            size_t gb = (size_t)(n0+row)*Cv + k0 + kk*8;
            *(uint4*)(sm+OFF_AH+so) = *(const uint4*)(Ah +ga);
            *(uint4*)(sm+OFF_AL+so) = *(const uint4*)(Al +ga);
            *(uint4*)(sm+OFF_BH+so) = *(const uint4*)(Bhb+gb);
            *(uint4*)(sm+OFF_BL+so) = *(const uint4*)(Blb+gb);
        }
        __syncthreads();
        #pragma unroll
        for (int k16 = 0; k16 < 4; k16++){
            uint32_t ah[2][4], al[2][4];
            #pragma unroll
            for (int fm = 0; fm < 2; fm++){
                int arow = warp_m*32 + fm*16 + a_row;
                uint32_t aaddr = smb + OFF_AH + arow*(RS*2) + (k16*16 + a_kc)*2;
                ldmatrix_x4(ah[fm], aaddr);
                ldmatrix_x4(al[fm], aaddr + (OFF_AL-OFF_AH));
            }
            #pragma unroll
            for (int half = 0; half < 2; half++){
                uint32_t bh[2][4], bl[2][4];
                #pragma unroll
                for (int p = 0; p < 2; p++){
                    int nrow = warp_n*64 + half*32 + p*16 + b_row;
                    uint32_t baddr = smb + OFF_BH + nrow*(RS*2) + (k16*16 + b_kc)*2;
                    ldmatrix_x4(bh[p], baddr);
                    ldmatrix_x4(bl[p], baddr + (OFF_BL-OFF_BH));
                }
                #pragma unroll
                for (int fm = 0; fm < 2; fm++)
                    #pragma unroll
                    for (int j = 0; j < 4; j++){
                        float* dd = d[fm][half*4+j];
                        uint32_t* fh = &bh[j>>1][(j&1)*2];
                        uint32_t* fl = &bl[j>>1][(j&1)*2];
                        mma_bf16(dd, ah[fm], fh[0], fh[1]);
                        mma_bf16(dd, ah[fm], fl[0], fl[1]);
                        mma_bf16(dd, al[fm], fh[0], fh[1]);
                    }
            }
        }
        __syncthreads();
    }

    float* stage = (float*)sm;            // [128][132]
    #pragma unroll
    for (int fm = 0; fm < 2; fm++)
        #pragma unroll
        for (int fn = 0; fn < 8; fn++){
            int row = warp_m*32 + fm*16 + (lane>>2);
            int col = warp_n*64 + fn*8 + 2*(lane&3);
            *(float2*)&stage[row*132+col]     = make_float2(d[fm][fn][0], d[fm][fn][1]);
            *(float2*)&stage[(row+8)*132+col] = make_float2(d[fm][fn][2], d[fm][fn][3]);
        }
    __syncthreads();

    if (mode == 0 || mode == 2){
        int col = tid & 127, mr0 = tid >> 7;
        #pragma unroll 8
        for (int it = 0; it < 64; it++){
            int m = it*2 + mr0;
            float v = stage[m*132 + col];
            size_t o = ((size_t)b*Mrows + m0 + m)*HWv + n0 + col;
            if (mode == 2) v += bias[m0+m] + resid[o];
            out[o] = v;
        }
    } else if (mode == 1){
        int n = tid >> 1;
        int mh = (tid & 1) * 64;
        size_t ro = ((size_t)b*HWv + n0 + n)*Cv + m0 + mh;
        #pragma unroll
        for (int c8 = 0; c8 < 8; c8++){
            uint4 hp, lp;
            bf16* hh = (bf16*)&hp; bf16* ll = (bf16*)&lp;
            #pragma unroll
            for (int i = 0; i < 8; i++){
                int m = mh + c8*8 + i;
                float v = gelu_f(stage[m*132 + n] + bias[m0 + m]);
                split_bf16(v, hh[i], ll[i]);
            }
            *(uint4*)&oxh[ro + c8*8] = hp;
            *(uint4*)&oxl[ro + c8*8] = lp;
        }
    } else if (mode == 3 || (mode == 4 && m0 < 256)){
        // K-major bf16 hi/lo out: [b][256][HW]
        int n2 = (tid & 63)*2, mr = tid >> 6;
        #pragma unroll 8
        for (int it = 0; it < 32; it++){
            int m = it*4 + mr;
            float v0 = stage[m*132 + n2], v1 = stage[m*132 + n2 + 1];
            bf16 hb[2], lb[2];
            split_bf16(v0, hb[0], lb[0]);
            split_bf16(v1, hb[1], lb[1]);
            size_t o = ((size_t)b*Cv + m0 + m)*HWv + n0 + n2;
            *(uint32_t*)&oxh[o] = *(uint32_t*)hb;
            *(uint32_t*)&oxl[o] = *(uint32_t*)lb;
        }
    } else {
        // mode 4, v-part: XT bf16 hi/lo into vt: [b][hw][256], c = m0-256+m
        int n = tid >> 1;
        int mh = (tid & 1) * 64;
        size_t ro = ((size_t)b*HWv + n0 + n)*Cv + (m0 - 256) + mh;
        #pragma unroll
        for (int c8 = 0; c8 < 8; c8++){
            uint4 hp, lp;
            bf16* hh = (bf16*)&hp; bf16* ll = (bf16*)&lp;
            #pragma unroll
            for (int i = 0; i < 8; i++){
                int m = mh + c8*8 + i;
                split_bf16(stage[m*132 + n], hh[i], ll[i]);
            }
            *(uint4*)&oxh2[ro + c8*8] = hp;
            *(uint4*)&oxl2[ro + c8*8] = lp;
        }
    }
}

// ---------------- reciprocal L2 row norms from bf16 hi/lo ----------------
__global__ __launch_bounds__(256) void rownorm_kernel(const bf16* __restrict__ xh,
        const bf16* __restrict__ xl, float* __restrict__ outinv)
{
    size_t base = (size_t)blockIdx.x * HWv;
    float s = 0.f;
    for (int h = threadIdx.x; h < HWv; h += 256){
        float v = __bfloat162float(xh[base+h]) + __bfloat162float(xl[base+h]);
        s += v*v;
    }
    #pragma unroll
    for (int o = 16; o > 0; o >>= 1) s += __shfl_xor_sync(0xffffffffu, s, o);
    __shared__ float red[8];
    if ((threadIdx.x & 31) == 0) red[threadIdx.x >> 5] = s;
    __syncthreads();
    if (threadIdx.x == 0){
        float t = 0.f;
        #pragma unroll
        for (int w = 0; w < 8; w++) t += red[w];
        outinv[blockIdx.x] = 1.f / fmaxf(sqrtf(t), 1e-12f);
    }
}

// ---------------- HMMA split-K raw S = q @ k^T  (split over HW, 4 splits) -------
__global__ __launch_bounds__(256) void attn_s_kernel()
{
    __shared__ __align__(16) char sm[36864];    // qh|ql|kh|kl, each 64 x 72 bf16
    uint32_t smb = smem_to_u32(sm);
    int tid = threadIdx.x, lane = tid & 31, warp = tid >> 5;
    int warp_m = warp & 3, warp_n = warp >> 2;
    int split = blockIdx.x;
    int sn = blockIdx.y, s = sn >> 2, n = sn & 3;
    int b = blockIdx.z;

    const bf16* srcs[4];
    srcs[0] = g_qb_h + ((size_t)b*Cv + n*HDv) * HWv;
    srcs[1] = g_qb_l + ((size_t)b*Cv + n*HDv) * HWv;
    srcs[2] = g_kb_h + ((size_t)(s*Bv + b)*Cv + n*HDv) * HWv;
    srcs[3] = g_kb_l + ((size_t)(s*Bv + b)*Cv + n*HDv) * HWv;

    int a_row = (lane & 7) + ((lane >> 3) & 1) * 8;
    int a_kc  = (lane >> 4) * 8;
    int b_row = (lane & 7) + (lane >> 4) * 8;
    int b_kc  = ((lane >> 3) & 1) * 8;

    float d[4][4];
    #pragma unroll
    for (int i=0;i<4;i++)
        #pragma unroll
        for (int j=0;j<4;j++) d[i][j] = 0.f;

    for (int kc = 0; kc < 16; kc++){
        int hwb = split*1024 + kc*64;
        #pragma unroll
        for (int arr = 0; arr < 4; arr++)
            #pragma unroll
            for (int hf = 0; hf < 2; hf++){
                int rem = tid + hf*256;
                int row = rem >> 3, c8 = rem & 7;
                *(uint4*)(sm + arr*9216 + row*144 + c8*16) =
                    *(const uint4*)(srcs[arr] + (size_t)row*HWv + hwb + c8*8);
            }
        __syncthreads();
        #pragma unroll
        for (int k16 = 0; k16 < 4; k16++){
            uint32_t ah[4], al[4];
            int arow = warp_m*16 + a_row;
            uint32_t abase = smb + arow*144 + (k16*16 + a_kc)*2;
            ldmatrix_x4(ah, abase);
            ldmatrix_x4(al, abase + 9216);
            #pragma unroll
            for (int p = 0; p < 2; p++){
                uint32_t bh[4], bl[4];
                int nrow = warp_n*32 + p*16 + b_row;
                uint32_t bbase = smb + 18432 + nrow*144 + (k16*16 + b_kc)*2;
                ldmatrix_x4(bh, bbase);
                ldmatrix_x4(bl, bbase + 9216);
                #pragma unroll
                for (int j = 0; j < 2; j++){
                    float* dd = d[p*2+j];
                    mma_bf16(dd, ah, bh[j*2], bh[j*2+1]);
                    mma_bf16(dd, ah, bl[j*2], bl[j*2+1]);
                    mma_bf16(dd, al, bh[j*2], bh[j*2+1]);
                }
            }
        }
        __syncthreads();
    }
    float* op = g_spart + ((((size_t)split*2 + s)*Bv + b)*NHv + n) * 4096;
    int r = warp_m*16 + (lane>>2);
    #pragma unroll
    for (int fn = 0; fn < 4; fn++){
        int col = warp_n*32 + fn*8 + 2*(lane&3);
        *(float2*)&op[r*64+col]     = make_float2(d[fn][0], d[fn][1]);
        *(float2*)&op[(r+8)*64+col] = make_float2(d[fn][2], d[fn][3]);
    }
}

// ---------------- sum partials, scale, softmax, fold gate -> bf16 hi/lo P -------
__global__ void attn_softmax_kernel(const float* __restrict__ attn_scale)
{
    int n = blockIdx.x, b = blockIdx.y, s = blockIdx.z;
    __shared__ float S[64][65];
    int tid = threadIdx.x;
    const float* qv  = g_qinv + b*Cv + n*HDv;
    const float* kvv = g_kinv + (s*Bv + b)*Cv + n*HDv;
    size_t moff = (((size_t)s*Bv + b)*NHv + n) * 4096;
    for (int idx = tid; idx < 4096; idx += 64){
        int c = idx >> 6, d = idx & 63;
        float a = 0.f;
        #pragma unroll
        for (int sp = 0; sp < 4; sp++)
            a += g_spart[((((size_t)sp*2 + s)*Bv + b)*NHv + n)*4096 + idx];
        S[c][d] = a * qv[c] * kvv[d];
    }
    __syncthreads();
    int c = tid;
    float g = 1.f / (1.f + expf(-attn_scale[n]));
    float factor = (s == 0) ? g : (1.f - g);
    float mx = -1e30f;
    for (int d = 0; d < 64; d++) mx = fmaxf(mx, S[c][d]);
    float sum = 0.f;
    for (int d = 0; d < 64; d++){ float e = expf(S[c][d] - mx); S[c][d] = e; sum += e; }
    float r = factor / sum;
    for (int d = 0; d < 64; d++){
        bf16 h, l;
        split_bf16(S[c][d] * r, h, l);
        g_ph[moff + c*64 + d] = h;
        g_pl[moff + c*64 + d] = l;
    }
}

// ---------------- HMMA qkv = Ptex@Vt + Pdep@Vd -> XT bf16 hi/lo ------------------
// smem: P arrays (4 x 64x72 bf16) then V arrays (4 x 128x72 bf16)
#define AVO_V 36864
#define AV_SMEM (36864 + 4*18432)
__global__ __launch_bounds__(256) void attn_av_kernel()
{
    extern __shared__ char sm[];
    uint32_t smb = smem_to_u32(sm);
    int tid = threadIdx.x, lane = tid & 31, warp = tid >> 5;
    int warp_m = warp & 3, warp_n = warp >> 2;
    int hw0 = blockIdx.x * 128;
    int n = blockIdx.y, b = blockIdx.z;

    size_t offT = (((size_t)0*Bv + b)*NHv + n) * 4096;
    size_t offD = (((size_t)1*Bv + b)*NHv + n) * 4096;
    const bf16* psrc[4] = {g_ph + offT, g_pl + offT, g_ph + offD, g_pl + offD};
    const bf16* vsrc[4];
    vsrc[0] = g_vt_h + (size_t)b*HWv*Cv;
    vsrc[1] = g_vt_l + (size_t)b*HWv*Cv;
    vsrc[2] = g_vt_h + (size_t)(Bv + b)*HWv*Cv;
    vsrc[3] = g_vt_l + (size_t)(Bv + b)*HWv*Cv;

    #pragma unroll
    for (int arr = 0; arr < 4; arr++)
        #pragma unroll
        for (int hf = 0; hf < 2; hf++){
            int rem = tid + hf*256;
            int row = rem >> 3, c8 = rem & 7;
            *(uint4*)(sm + arr*9216 + row*144 + c8*16) =
                *(const uint4*)(psrc[arr] + row*64 + c8*8);
        }
    #pragma unroll
    for (int arr = 0; arr < 4; arr++)
        #pragma unroll
        for (int hf = 0; hf < 4; hf++){
            int rem = tid + hf*256;
            int row = rem >> 3, c8 = rem & 7;
            *(uint4*)(sm + AVO_V + arr*18432 + row*144 + c8*16) =
                *(const uint4*)(vsrc[arr] + (size_t)(hw0+row)*Cv + n*HDv + c8*8);
        }
    __syncthreads();

    int a_row = (lane & 7) + ((lane >> 3) & 1) * 8;
    int a_kc  = (lane >> 4) * 8;
    int b_row = (lane & 7) + (lane >> 4) * 8;
    int b_kc  = ((lane >> 3) & 1) * 8;

    float d[8][4];
    #pragma unroll
    for (int i=0;i<8;i++)
        #pragma unroll
        for (int j=0;j<4;j++) d[i][j] = 0.f;

    #pragma unroll
    for (int k16 = 0; k16 < 4; k16++){
        uint32_t ath[4], atl[4], adh[4], adl[4];
        int arow = warp_m*16 + a_row;
        uint32_t abase = smb + arow*144 + (k16*16 + a_kc)*2;
        ldmatrix_x4(ath, abase);
        ldmatrix_x4(atl, abase + 9216);
        ldmatrix_x4(adh, abase + 18432);
        ldmatrix_x4(adl, abase + 27648);
        #pragma unroll
        for (int p = 0; p < 4; p++){
            uint32_t bth[4], btl[4], bdh[4], bdl[4];
            int nrow = warp_n*64 + p*16 + b_row;
            uint32_t bbase = smb + AVO_V + nrow*144 + (k16*16 + b_kc)*2;
            ldmatrix_x4(bth, bbase);
            ldmatrix_x4(btl, bbase + 18432);
            ldmatrix_x4(bdh, bbase + 36864);
            ldmatrix_x4(bdl, bbase + 55296);
            #pragma unroll
            for (int j = 0; j < 2; j++){
                float* dd = d[p*2+j];
                mma_bf16(dd, ath, bth[j*2], bth[j*2+1]);
                mma_bf16(dd, ath, btl[j*2], btl[j*2+1]);
                mma_bf16(dd, atl, bth[j*2], bth[j*2+1]);
                mma_bf16(dd, adh, bdh[j*2], bdh[j*2+1]);
                mma_bf16(dd, adh, bdl[j*2], bdl[j*2+1]);
                mma_bf16(dd, adl, bdh[j*2], bdh[j*2+1]);
            }
        }
    }
    __syncthreads();
    float* stage = (float*)sm;          // [64][132]
    int r = warp_m*16 + (lane>>2);
    #pragma unroll
    for (int fn = 0; fn < 8; fn++){
        int col = warp_n*64 + fn*8 + 2*(lane&3);
        *(float2*)&stage[r*132+col]     = make_float2(d[fn][0], d[fn][1]);
        *(float2*)&stage[(r+8)*132+col] = make_float2(d[fn][2], d[fn][3]);
    }
    __syncthreads();
    int hw_l = tid >> 1, c0 = (tid & 1) * 32;
    #pragma unroll
    for (int q4 = 0; q4 < 4; q4++){
        uint4 hp, lp;
        bf16* hh = (bf16*)&hp; bf16* ll = (bf16*)&lp;
        #pragma unroll
        for (int i = 0; i < 8; i++){
            float v = stage[(c0 + q4*8 + i)*132 + hw_l];
            split_bf16(v, hh[i], ll[i]);
        }
        size_t ro = ((size_t)b*HWv + hw0 + hw_l)*Cv + n*HDv + c0 + q4*8;
        *(uint4*)&g_xqkv_h[ro] = hp;
        *(uint4*)&g_xqkv_l[ro] = lp;
    }
}

// ---------------- host launcher ----------------
extern "C" void kernel_launch(void* const* d_in, const int* in_sizes, int n_in,
                              void* d_out, int out_size)
{
    const float* img    = (const float*)d_in[0];
    const float* aux0   = (const float*)d_in[1];
    const float* aux1   = (const float*)d_in[2];
    const float* qlnw   = (const float*)d_in[3];
    const float* qlnb   = (const float*)d_in[4];
    const float* kvlnw  = (const float*)d_in[5];
    const float* kvlnb  = (const float*)d_in[6];
    const float* Wq     = (const float*)d_in[7];
    const float* Wkv    = (const float*)d_in[8];
    const float* Wo     = (const float*)d_in[9];
    const float* bo     = (const float*)d_in[10];
    const float* ascale = (const float*)d_in[11];
    const float* mlnw   = (const float*)d_in[12];
    const float* mlnb   = (const float*)d_in[13];
    const float* W1     = (const float*)d_in[14];
    const float* b1     = (const float*)d_in[15];
    const float* W2     = (const float*)d_in[16];
    const float* b2     = (const float*)d_in[17];

    bf16 *xa_h,*xa_l,*xkv_h,*xkv_l,*xqkv_h,*xqkv_l,*xh_h,*xh_l,*wh,*wl;
    bf16 *qb_h,*qb_l,*kb_h,*kb_l,*vt_h,*vt_l;
    float *xbuf,*qinv,*kinv;
    cudaGetSymbolAddress((void**)&xa_h,  g_xa_h);
    cudaGetSymbolAddress((void**)&xa_l,  g_xa_l);
    cudaGetSymbolAddress((void**)&xkv_h, g_xkv_h);
    cudaGetSymbolAddress((void**)&xkv_l, g_xkv_l);
    cudaGetSymbolAddress((void**)&xqkv_h,g_xqkv_h);
    cudaGetSymbolAddress((void**)&xqkv_l,g_xqkv_l);
    cudaGetSymbolAddress((void**)&xh_h,  g_xh_h);
    cudaGetSymbolAddress((void**)&xh_l,  g_xh_l);
    cudaGetSymbolAddress((void**)&wh,    g_w_h);
    cudaGetSymbolAddress((void**)&wl,    g_w_l);
    cudaGetSymbolAddress((void**)&qb_h,  g_qb_h);
    cudaGetSymbolAddress((void**)&qb_l,  g_qb_l);
    cudaGetSymbolAddress((void**)&kb_h,  g_kb_h);
    cudaGetSymbolAddress((void**)&kb_l,  g_kb_l);
    cudaGetSymbolAddress((void**)&vt_h,  g_vt_h);
    cudaGetSymbolAddress((void**)&vt_l,  g_vt_l);
    cudaGetSymbolAddress((void**)&xbuf,  g_x);
    cudaGetSymbolAddress((void**)&qinv,  g_qinv);
    cudaGetSymbolAddress((void**)&kinv,  g_kinv);

    cudaFuncSetAttribute(gemm_kernel,
                         cudaFuncAttributeMaxDynamicSharedMemorySize, GEMM_SMEM);
    cudaFuncSetAttribute(attn_av_kernel,
                         cudaFuncAttributeMaxDynamicSharedMemorySize, AV_SMEM);

    const int WQ_O = 0, WKV_O = 65536, WO_O = 196608, W1_O = 262144, W2_O = 327680;

    // 0. weight conversion
    wconv_kernel<<<256,256>>>(Wq,  wh+WQ_O,  wl+WQ_O,  65536);
    wconv_kernel<<<512,256>>>(Wkv, wh+WKV_O, wl+WKV_O, 131072);
    wconv_kernel<<<256,256>>>(Wo,  wh+WO_O,  wl+WO_O,  65536);
    wconv_kernel<<<256,256>>>(W1,  wh+W1_O,  wl+W1_O,  65536);
    wconv_kernel<<<256,256>>>(W2,  wh+W2_O,  wl+W2_O,  65536);

    const int LNB = (Bv*HWv)/256;   // 128

    // 1. LayerNorms -> transposed bf16 hi/lo activations
    ln_xt_kernel<<<LNB,256>>>(img,  qlnw,  qlnb,  xa_h,  xa_l);
    ln_xt_kernel<<<LNB,256>>>(aux0, kvlnw, kvlnb, xkv_h, xkv_l);
    ln_xt_kernel<<<LNB,256>>>(aux1, kvlnw, kvlnb,
                              xkv_h + (size_t)Bv*HWv*Cv, xkv_l + (size_t)Bv*HWv*Cv);

    // 2. Projections (HMMA bf16x3) -> bf16 hi/lo MMA-ready layouts
    gemm_kernel<<<dim3(32,2,Bv),   256, GEMM_SMEM>>>(wh+WQ_O,  wl+WQ_O,  xa_h,  xa_l,
        nullptr, qb_h, qb_l, nullptr, nullptr, nullptr, nullptr, 3, 256);
    gemm_kernel<<<dim3(32,4,2*Bv), 256, GEMM_SMEM>>>(wh+WKV_O, wl+WKV_O, xkv_h, xkv_l,
        nullptr, kb_h, kb_l, vt_h, vt_l, nullptr, nullptr, 4, 512);

    // 3. Reciprocal row norms (from bf16 hi/lo)
    rownorm_kernel<<<Bv*Cv,   256>>>(qb_h, qb_l, qinv);
    rownorm_kernel<<<2*Bv*Cv, 256>>>(kb_h, kb_l, kinv);

    // 4. Attention (HMMA)
    attn_s_kernel      <<<dim3(4, 2*NHv, Bv), 256>>>();
    attn_softmax_kernel<<<dim3(NHv, Bv, 2),    64>>>(ascale);
    attn_av_kernel     <<<dim3(HWv/128, NHv, Bv), 256, AV_SMEM>>>();

    // 5. x = img + Wo@qkv + bo
    gemm_kernel<<<dim3(32,2,Bv), 256, GEMM_SMEM>>>(wh+WO_O, wl+WO_O, xqkv_h, xqkv_l,
        xbuf, nullptr, nullptr, nullptr, nullptr, bo, img, 2, 256);

    // 6. MLP
    ln_xt_kernel<<<LNB,256>>>(xbuf, mlnw, mlnb, xa_h, xa_l);
    gemm_kernel<<<dim3(32,2,Bv), 256, GEMM_SMEM>>>(wh+W1_O, wl+W1_O, xa_h, xa_l,
        nullptr, xh_h, xh_l, nullptr, nullptr, b1, nullptr, 1, 256);
    gemm_kernel<<<dim3(32,2,Bv), 256, GEMM_SMEM>>>(wh+W2_O, wl+W2_O, xh_h, xh_l,
        (float*)d_out, nullptr, nullptr, nullptr, nullptr, b2, xbuf, 2, 256);
}